// round 1
// baseline (speedup 1.0000x reference)
#include <cuda_runtime.h>
#include <math.h>

// Problem constants
#define T_      1024
#define D_      1024
#define E_      16
#define K_SEL   4
#define NGRP    4
#define INTER_  512
#define SH_INTER 1024
#define RSCALE  2.5f

// GEMM tiling
#define BM 64
#define BN 64
#define BK 16

// ---------------- device scratch (no allocations allowed) ----------------
__device__ int   g_cnt[E_];
__device__ int   g_tok[E_ * T_];
__device__ float g_wt [E_ * T_];
__device__ float g_inter[(size_t)E_ * T_ * INTER_];   // 32 MB: per-expert SwiGLU activations
__device__ float g_hsh[(size_t)T_ * SH_INTER];        // 4 MB: shared-expert activations

// ---------------- kernels ----------------
__global__ void zero_counts_kernel() {
    if (threadIdx.x < E_) g_cnt[threadIdx.x] = 0;
}

// One block per token: 16 sigmoid scores + group-limited top-k routing.
__global__ void route_kernel(const float* __restrict__ x,
                             const float* __restrict__ gw,
                             const float* __restrict__ gb) {
    const int t = blockIdx.x;
    __shared__ float xs[D_];
    __shared__ float sc[E_];
    const int tid = threadIdx.x;                 // 128 threads
    // load x row (float4 vectorized)
    const float4* xr = (const float4*)(x + (size_t)t * D_);
    float4* xs4 = (float4*)xs;
    for (int i = tid; i < D_ / 4; i += 128) xs4[i] = xr[i];
    __syncthreads();

    const int warp = tid >> 5, lane = tid & 31;
    for (int e = warp * 4; e < warp * 4 + 4; e++) {
        const float* w = gw + (size_t)e * D_;
        float p = 0.f;
        for (int j = lane; j < D_; j += 32) p += xs[j] * w[j];
        #pragma unroll
        for (int o = 16; o; o >>= 1) p += __shfl_xor_sync(0xffffffffu, p, o);
        if (lane == 0) sc[e] = 1.f / (1.f + expf(-p));
    }
    __syncthreads();

    if (tid == 0) {
        float s[E_];
        #pragma unroll
        for (int e = 0; e < E_; e++) s[e] = sc[e] + gb[e];
        // per-group sum of top-2
        float gsc[NGRP];
        #pragma unroll
        for (int g = 0; g < NGRP; g++) {
            float m1 = -1e30f, m2 = -1e30f;
            #pragma unroll
            for (int j = 0; j < 4; j++) {
                float v = s[g * 4 + j];
                if (v > m1) { m2 = m1; m1 = v; } else if (v > m2) { m2 = v; }
            }
            gsc[g] = m1 + m2;
        }
        // top-2 groups (first index wins ties, matching jax.lax.top_k)
        int g1 = 0;
        for (int g = 1; g < NGRP; g++) if (gsc[g] > gsc[g1]) g1 = g;
        int g2 = -1;
        for (int g = 0; g < NGRP; g++) {
            if (g == g1) continue;
            if (g2 < 0 || gsc[g] > gsc[g2]) g2 = g;
        }
        float masked[E_];
        #pragma unroll
        for (int e = 0; e < E_; e++) {
            int g = e >> 2;
            masked[e] = (g == g1 || g == g2) ? s[e] : 0.f;
        }
        // top-4 experts among masked (sigmoid scores > 0, so always in-group)
        int   idx[K_SEL];
        float w[K_SEL];
        bool  used[E_];
        #pragma unroll
        for (int e = 0; e < E_; e++) used[e] = false;
        float wsum = 0.f;
        for (int k = 0; k < K_SEL; k++) {
            int best = -1; float bv = -1e30f;
            for (int e = 0; e < E_; e++) {
                if (used[e]) continue;
                if (masked[e] > bv) { bv = masked[e]; best = e; }
            }
            used[best] = true;
            idx[k] = best;
            w[k] = sc[best];          // original (unbiased) sigmoid score
            wsum += w[k];
        }
        const float scale = RSCALE / wsum;
        for (int k = 0; k < K_SEL; k++) {
            int e = idx[k];
            int pos = atomicAdd(&g_cnt[e], 1);
            g_tok[e * T_ + pos] = t;
            g_wt [e * T_ + pos] = w[k] * scale;
        }
    }
}

// Fused gate+up GEMM with SiLU epilogue.
// GATHER=true : per-expert gathered rows of x -> g_inter[e]
// GATHER=false: shared expert, dense rows of x -> g_hsh
template <bool GATHER>
__global__ void __launch_bounds__(256) gemm1_kernel(const float* __restrict__ X,
                                                    const float* __restrict__ Wg_,
                                                    const float* __restrict__ Wu_) {
    constexpr int K = D_;
    const int e   = GATHER ? blockIdx.z : 0;
    const int cnt = GATHER ? g_cnt[e] : T_;
    const int m0  = blockIdx.y * BM;
    if (m0 >= cnt) return;
    const int n0 = blockIdx.x * BN;

    const float* Wg = Wg_ + (GATHER ? (size_t)e * INTER_ * D_ : 0);
    const float* Wu = Wu_ + (GATHER ? (size_t)e * INTER_ * D_ : 0);
    float* C        = GATHER ? (g_inter + (size_t)e * T_ * INTER_) : g_hsh;
    const int ldc   = GATHER ? INTER_ : SH_INTER;

    __shared__ float As[BK][BM];
    __shared__ float Bg[BK][BN];
    __shared__ float Bu[BK][BN];

    const int tid = threadIdx.x;
    const int lr = tid >> 2;             // 0..63
    const int lc = (tid & 3) << 2;       // 0,4,8,12

    int mm = m0 + lr;
    if (mm > cnt - 1) mm = cnt - 1;
    const int arow = GATHER ? g_tok[e * T_ + mm] : mm;
    const float* Ap  = X  + (size_t)arow * K + lc;
    const float* Wgp = Wg + (size_t)(n0 + lr) * K + lc;
    const float* Wup = Wu + (size_t)(n0 + lr) * K + lc;

    const int ty = tid >> 4, tx = tid & 15;
    float acg[4][4] = {{0.f}}, acu[4][4] = {{0.f}};

    for (int k0 = 0; k0 < K; k0 += BK) {
        float4 av = *(const float4*)(Ap  + k0);
        float4 gv = *(const float4*)(Wgp + k0);
        float4 uv = *(const float4*)(Wup + k0);
        As[lc + 0][lr] = av.x; As[lc + 1][lr] = av.y; As[lc + 2][lr] = av.z; As[lc + 3][lr] = av.w;
        Bg[lc + 0][lr] = gv.x; Bg[lc + 1][lr] = gv.y; Bg[lc + 2][lr] = gv.z; Bg[lc + 3][lr] = gv.w;
        Bu[lc + 0][lr] = uv.x; Bu[lc + 1][lr] = uv.y; Bu[lc + 2][lr] = uv.z; Bu[lc + 3][lr] = uv.w;
        __syncthreads();
        #pragma unroll
        for (int kk = 0; kk < BK; kk++) {
            float4 a  = *(const float4*)&As[kk][ty * 4];
            float4 bg = *(const float4*)&Bg[kk][tx * 4];
            float4 bu = *(const float4*)&Bu[kk][tx * 4];
            float aa[4]  = {a.x, a.y, a.z, a.w};
            float bgv[4] = {bg.x, bg.y, bg.z, bg.w};
            float buv[4] = {bu.x, bu.y, bu.z, bu.w};
            #pragma unroll
            for (int i = 0; i < 4; i++)
                #pragma unroll
                for (int j = 0; j < 4; j++) {
                    acg[i][j] += aa[i] * bgv[j];
                    acu[i][j] += aa[i] * buv[j];
                }
        }
        __syncthreads();
    }

    #pragma unroll
    for (int i = 0; i < 4; i++) {
        int m = m0 + ty * 4 + i;
        if (m >= cnt) continue;
        float vals[4];
        #pragma unroll
        for (int j = 0; j < 4; j++) {
            float g = acg[i][j];
            float sig = 1.f / (1.f + expf(-g));
            vals[j] = g * sig * acu[i][j];
        }
        float* cp = C + (size_t)m * ldc + n0 + tx * 4;
        *(float4*)cp = make_float4(vals[0], vals[1], vals[2], vals[3]);
    }
}

// Down-projection GEMM.
// SCATTER=true : A = g_inter[e], atomicAdd weighted rows into out[token]
// SCATTER=false: A = g_hsh (shared expert), plain store into out (initializes it)
template <bool SCATTER>
__global__ void __launch_bounds__(256) gemm2_kernel(const float* __restrict__ Wd_,
                                                    float* __restrict__ out) {
    constexpr int K = SCATTER ? INTER_ : SH_INTER;
    const int e   = SCATTER ? blockIdx.z : 0;
    const int cnt = SCATTER ? g_cnt[e] : T_;
    const int m0  = blockIdx.y * BM;
    if (m0 >= cnt) return;
    const int n0 = blockIdx.x * BN;

    const float* A = SCATTER ? (g_inter + (size_t)e * T_ * INTER_) : g_hsh;
    const float* W = Wd_ + (SCATTER ? (size_t)e * D_ * INTER_ : 0);

    __shared__ float As[BK][BM];
    __shared__ float Bs[BK][BN];

    const int tid = threadIdx.x;
    const int lr = tid >> 2;
    const int lc = (tid & 3) << 2;

    int mm = m0 + lr;
    if (mm > cnt - 1) mm = cnt - 1;
    const float* Ap = A + (size_t)mm * K + lc;
    const float* Wp = W + (size_t)(n0 + lr) * K + lc;

    const int ty = tid >> 4, tx = tid & 15;
    float acc[4][4] = {{0.f}};

    for (int k0 = 0; k0 < K; k0 += BK) {
        float4 av = *(const float4*)(Ap + k0);
        float4 bv = *(const float4*)(Wp + k0);
        As[lc + 0][lr] = av.x; As[lc + 1][lr] = av.y; As[lc + 2][lr] = av.z; As[lc + 3][lr] = av.w;
        Bs[lc + 0][lr] = bv.x; Bs[lc + 1][lr] = bv.y; Bs[lc + 2][lr] = bv.z; Bs[lc + 3][lr] = bv.w;
        __syncthreads();
        #pragma unroll
        for (int kk = 0; kk < BK; kk++) {
            float4 a = *(const float4*)&As[kk][ty * 4];
            float4 b = *(const float4*)&Bs[kk][tx * 4];
            float aa[4] = {a.x, a.y, a.z, a.w};
            float bb[4] = {b.x, b.y, b.z, b.w};
            #pragma unroll
            for (int i = 0; i < 4; i++)
                #pragma unroll
                for (int j = 0; j < 4; j++)
                    acc[i][j] += aa[i] * bb[j];
        }
        __syncthreads();
    }

    #pragma unroll
    for (int i = 0; i < 4; i++) {
        int m = m0 + ty * 4 + i;
        if (m >= cnt) continue;
        if (SCATTER) {
            int   t  = g_tok[e * T_ + m];
            float wt = g_wt [e * T_ + m];
            float* op = out + (size_t)t * D_ + n0 + tx * 4;
            #pragma unroll
            for (int j = 0; j < 4; j++) atomicAdd(op + j, wt * acc[i][j]);
        } else {
            float* op = out + (size_t)m * D_ + n0 + tx * 4;
            *(float4*)op = make_float4(acc[i][0], acc[i][1], acc[i][2], acc[i][3]);
        }
    }
}

// ---------------- launch ----------------
extern "C" void kernel_launch(void* const* d_in, const int* in_sizes, int n_in,
                              void* d_out, int out_size) {
    const float* x  = (const float*)d_in[0];
    // d_in[1] = token_mask (all ones, unused by the reference math)
    const float* gw = (const float*)d_in[2];
    const float* gb = (const float*)d_in[3];
    const float* gp = (const float*)d_in[4];
    const float* up = (const float*)d_in[5];
    const float* dp = (const float*)d_in[6];
    const float* sg = (const float*)d_in[7];
    const float* su = (const float*)d_in[8];
    const float* sd = (const float*)d_in[9];
    float* out = (float*)d_out;

    zero_counts_kernel<<<1, 32>>>();
    route_kernel<<<T_, 128>>>(x, gw, gb);

    // shared expert: gate/up -> g_hsh, then down writes out (full init)
    gemm1_kernel<false><<<dim3(SH_INTER / BN, T_ / BM), 256>>>(x, sg, su);
    gemm2_kernel<false><<<dim3(D_ / BN, T_ / BM), 256>>>(sd, out);

    // routed experts (sparse): gate/up -> g_inter, down atomic-adds into out
    gemm1_kernel<true><<<dim3(INTER_ / BN, T_ / BM, E_), 256>>>(x, gp, up);
    gemm2_kernel<true><<<dim3(D_ / BN, T_ / BM, E_), 256>>>(dp, out);
}

// round 3
// speedup vs baseline: 2.5798x; 2.5798x over previous
#include <cuda_runtime.h>
#include <math.h>
#include <stdint.h>

// Problem constants
#define T_       1024
#define D_       1024
#define E_       16
#define K_SEL    4
#define NGRP     4
#define INTER_   512
#define SH_INTER 1024
#define RSCALE   2.5f

#define LDP 36   // padded smem row stride in floats (128B rows + 16B pad)

// ---------------- device scratch (no allocations allowed) ----------------
__device__ int   g_cnt[E_];
__device__ int   g_tok[E_ * T_];
__device__ float g_wt [E_ * T_];
__device__ float g_inter[(size_t)E_ * T_ * INTER_];   // per-expert SwiGLU activations (compacted rows)
__device__ float g_hsh[(size_t)T_ * SH_INTER];        // shared-expert activations

// ---------------- helpers ----------------
__device__ __forceinline__ float to_tf32_rna(float f) {
    uint32_t u;
    asm("cvt.rna.tf32.f32 %0, %1;" : "=r"(u) : "f"(f));
    return __uint_as_float(u);
}
__device__ __forceinline__ float4 rna4(float4 v) {
    return make_float4(to_tf32_rna(v.x), to_tf32_rna(v.y), to_tf32_rna(v.z), to_tf32_rna(v.w));
}
__device__ __forceinline__ void mma_tf32(float c[4],
                                         uint32_t a0, uint32_t a1, uint32_t a2, uint32_t a3,
                                         uint32_t b0, uint32_t b1) {
    asm volatile(
        "mma.sync.aligned.m16n8k8.row.col.f32.tf32.tf32.f32 "
        "{%0,%1,%2,%3}, {%4,%5,%6,%7}, {%8,%9}, {%0,%1,%2,%3};"
        : "+f"(c[0]), "+f"(c[1]), "+f"(c[2]), "+f"(c[3])
        : "r"(a0), "r"(a1), "r"(a2), "r"(a3), "r"(b0), "r"(b1));
}
__device__ __forceinline__ float silu_mul(float g, float u) {
    return g / (1.f + expf(-g)) * u;
}

// ---------------- routing ----------------
__global__ void zero_counts_kernel() {
    if (threadIdx.x < E_) g_cnt[threadIdx.x] = 0;
}

__global__ void route_kernel(const float* __restrict__ x,
                             const float* __restrict__ gw,
                             const float* __restrict__ gb) {
    const int t = blockIdx.x;
    __shared__ float xs[D_];
    __shared__ float sc[E_];
    const int tid = threadIdx.x;  // 128
    const float4* xr = (const float4*)(x + (size_t)t * D_);
    float4* xs4 = (float4*)xs;
    for (int i = tid; i < D_ / 4; i += 128) xs4[i] = xr[i];
    __syncthreads();

    const int warp = tid >> 5, lane = tid & 31;
    for (int e = warp * 4; e < warp * 4 + 4; e++) {
        const float* w = gw + (size_t)e * D_;
        float p = 0.f;
        for (int j = lane; j < D_; j += 32) p += xs[j] * w[j];
        #pragma unroll
        for (int o = 16; o; o >>= 1) p += __shfl_xor_sync(0xffffffffu, p, o);
        if (lane == 0) sc[e] = 1.f / (1.f + expf(-p));
    }
    __syncthreads();

    if (tid == 0) {
        float s[E_];
        #pragma unroll
        for (int e = 0; e < E_; e++) s[e] = sc[e] + gb[e];
        float gsc[NGRP];
        #pragma unroll
        for (int g = 0; g < NGRP; g++) {
            float m1 = -1e30f, m2 = -1e30f;
            #pragma unroll
            for (int j = 0; j < 4; j++) {
                float v = s[g * 4 + j];
                if (v > m1) { m2 = m1; m1 = v; } else if (v > m2) { m2 = v; }
            }
            gsc[g] = m1 + m2;
        }
        int g1 = 0;
        for (int g = 1; g < NGRP; g++) if (gsc[g] > gsc[g1]) g1 = g;
        int g2 = -1;
        for (int g = 0; g < NGRP; g++) {
            if (g == g1) continue;
            if (g2 < 0 || gsc[g] > gsc[g2]) g2 = g;
        }
        float masked[E_];
        #pragma unroll
        for (int e = 0; e < E_; e++) {
            int g = e >> 2;
            masked[e] = (g == g1 || g == g2) ? s[e] : 0.f;
        }
        int idx[K_SEL];
        float w[K_SEL];
        bool used[E_];
        #pragma unroll
        for (int e = 0; e < E_; e++) used[e] = false;
        float wsum = 0.f;
        for (int k = 0; k < K_SEL; k++) {
            int best = -1; float bv = -1e30f;
            for (int e = 0; e < E_; e++) {
                if (used[e]) continue;
                if (masked[e] > bv) { bv = masked[e]; best = e; }
            }
            used[best] = true;
            idx[k] = best;
            w[k] = sc[best];
            wsum += w[k];
        }
        const float scale = RSCALE / wsum;
        for (int k = 0; k < K_SEL; k++) {
            int e = idx[k];
            int pos = atomicAdd(&g_cnt[e], 1);
            g_tok[e * T_ + pos] = t;
            g_wt [e * T_ + pos] = w[k] * scale;
        }
    }
}

// ================================================================
// GEMM 1: C[m, n] = silu(X Wg^T) * (X Wu^T), tf32 mma.sync
// Block: M=128 rows x N=64 (gate cols; up computed in parallel).
// B smem rows 0..63 = gate weights n0..n0+63, rows 64..127 = up weights.
// 8 warps: wm in {0,1} (64 rows each), wn in {0..3} (16 gate cols each).
// ================================================================
template <bool GATHER>
__global__ void __launch_bounds__(256) mma_gu_kernel(const float* __restrict__ X,
                                                     const float* __restrict__ Wg_,
                                                     const float* __restrict__ Wu_) {
    const int e   = GATHER ? blockIdx.z : 0;
    const int cnt = GATHER ? g_cnt[e] : T_;
    const int m0  = blockIdx.y * 128;
    if (m0 >= cnt) return;
    const int n0 = blockIdx.x * 64;

    const float* Wg = Wg_ + (GATHER ? (size_t)e * INTER_ * D_ : 0);
    const float* Wu = Wu_ + (GATHER ? (size_t)e * INTER_ * D_ : 0);
    float* C        = GATHER ? (g_inter + (size_t)e * T_ * INTER_) : g_hsh;
    const int ldc   = GATHER ? INTER_ : SH_INTER;

    extern __shared__ float smem[];
    float* As = smem;                    // [2][128][LDP]
    float* Bs = smem + 2 * 128 * LDP;    // [2][128][LDP]

    const int tid = threadIdx.x, wid = tid >> 5, lane = tid & 31;
    const int wm = wid >> 2, wn = wid & 3;

    // ---- per-thread global load plan: 4 A float4 + 4 B float4 per stage ----
    const float4* asrc[4]; const float4* bsrc[4];
    int sts_off[4];
    #pragma unroll
    for (int t = 0; t < 4; t++) {
        int it = tid + 256 * t;
        int row = it >> 3, c4 = it & 7;
        int mm = m0 + row; if (mm > cnt - 1) mm = cnt - 1;
        int ar = GATHER ? g_tok[e * T_ + mm] : mm;
        asrc[t] = (const float4*)(X + (size_t)ar * D_) + c4;
        const float* bbase = (row < 64) ? (Wg + (size_t)(n0 + row) * D_)
                                        : (Wu + (size_t)(n0 + row - 64) * D_);
        bsrc[t] = (const float4*)bbase + c4;
        sts_off[t] = row * LDP + c4 * 4;
    }

    float acg[4][2][4], acu[4][2][4];
    #pragma unroll
    for (int mi = 0; mi < 4; mi++)
        #pragma unroll
        for (int nj = 0; nj < 2; nj++)
            #pragma unroll
            for (int r = 0; r < 4; r++) { acg[mi][nj][r] = 0.f; acu[mi][nj][r] = 0.f; }

    const int NS = D_ / 32;
    float4 ra[4], rb[4];
    #pragma unroll
    for (int t = 0; t < 4; t++) { ra[t] = asrc[t][0]; rb[t] = bsrc[t][0]; }
    {   // prologue: fill buffer 0
        float* Ab = As; float* Bb = Bs;
        #pragma unroll
        for (int t = 0; t < 4; t++) {
            *(float4*)(Ab + sts_off[t]) = rna4(ra[t]);
            *(float4*)(Bb + sts_off[t]) = rna4(rb[t]);
        }
    }
    __syncthreads();

    for (int s = 0; s < NS; s++) {
        const int buf = s & 1;
        if (s + 1 < NS) {
            #pragma unroll
            for (int t = 0; t < 4; t++) { ra[t] = asrc[t][(s + 1) * 8]; rb[t] = bsrc[t][(s + 1) * 8]; }
        }
        const float* Ab = As + buf * 128 * LDP;
        const float* Bb = Bs + buf * 128 * LDP;
        const int q = lane >> 2, c = lane & 3;
        #pragma unroll
        for (int ks = 0; ks < 4; ks++) {
            const int kc = ks * 8 + c;
            uint32_t af[4][4];
            #pragma unroll
            for (int mi = 0; mi < 4; mi++) {
                const int r = wm * 64 + mi * 16 + q;
                af[mi][0] = __float_as_uint(Ab[r * LDP + kc]);
                af[mi][1] = __float_as_uint(Ab[(r + 8) * LDP + kc]);
                af[mi][2] = __float_as_uint(Ab[r * LDP + kc + 4]);
                af[mi][3] = __float_as_uint(Ab[(r + 8) * LDP + kc + 4]);
            }
            #pragma unroll
            for (int nj = 0; nj < 2; nj++) {
                const int n = wn * 16 + nj * 8 + q;
                uint32_t bg0 = __float_as_uint(Bb[n * LDP + kc]);
                uint32_t bg1 = __float_as_uint(Bb[n * LDP + kc + 4]);
                uint32_t bu0 = __float_as_uint(Bb[(n + 64) * LDP + kc]);
                uint32_t bu1 = __float_as_uint(Bb[(n + 64) * LDP + kc + 4]);
                #pragma unroll
                for (int mi = 0; mi < 4; mi++) {
                    mma_tf32(acg[mi][nj], af[mi][0], af[mi][1], af[mi][2], af[mi][3], bg0, bg1);
                    mma_tf32(acu[mi][nj], af[mi][0], af[mi][1], af[mi][2], af[mi][3], bu0, bu1);
                }
            }
        }
        if (s + 1 < NS) {
            __syncthreads();
            float* Aw = As + (buf ^ 1) * 128 * LDP;
            float* Bw = Bs + (buf ^ 1) * 128 * LDP;
            #pragma unroll
            for (int t = 0; t < 4; t++) {
                *(float4*)(Aw + sts_off[t]) = rna4(ra[t]);
                *(float4*)(Bw + sts_off[t]) = rna4(rb[t]);
            }
            __syncthreads();
        }
    }

    // ---- epilogue: SwiGLU, write C ----
    const int q = lane >> 2, c2 = (lane & 3) * 2;
    #pragma unroll
    for (int mi = 0; mi < 4; mi++) {
        const int r0 = m0 + wm * 64 + mi * 16 + q;
        #pragma unroll
        for (int nj = 0; nj < 2; nj++) {
            const int col = n0 + wn * 16 + nj * 8 + c2;
            if (r0 < cnt) {
                float2 v = make_float2(silu_mul(acg[mi][nj][0], acu[mi][nj][0]),
                                       silu_mul(acg[mi][nj][1], acu[mi][nj][1]));
                *(float2*)(C + (size_t)r0 * ldc + col) = v;
            }
            if (r0 + 8 < cnt) {
                float2 v = make_float2(silu_mul(acg[mi][nj][2], acu[mi][nj][2]),
                                       silu_mul(acg[mi][nj][3], acu[mi][nj][3]));
                *(float2*)(C + (size_t)(r0 + 8) * ldc + col) = v;
            }
        }
    }
}

// ================================================================
// GEMM 2: out = A Wd^T.  Block M=128 x N=128.
// 8 warps: wm in {0,1} (64 rows), wn in {0..3} (32 cols, 4 n-frags).
// SCATTER: A = compacted g_inter[e], atomicAdd weighted rows into out.
// else:    A = g_hsh, plain store (initializes out).
// ================================================================
template <bool SCATTER, int KD>
__global__ void __launch_bounds__(256) mma_down_kernel(const float* __restrict__ Wd_,
                                                       float* __restrict__ out) {
    const int e   = SCATTER ? blockIdx.z : 0;
    const int cnt = SCATTER ? g_cnt[e] : T_;
    const int m0  = blockIdx.y * 128;
    if (m0 >= cnt) return;
    const int n0 = blockIdx.x * 128;

    const float* A = SCATTER ? (g_inter + (size_t)e * T_ * INTER_) : g_hsh;
    const float* W = Wd_ + (SCATTER ? (size_t)e * D_ * INTER_ : 0);

    extern __shared__ float smem[];
    float* As = smem;
    float* Bs = smem + 2 * 128 * LDP;

    const int tid = threadIdx.x, wid = tid >> 5, lane = tid & 31;
    const int wm = wid >> 2, wn = wid & 3;

    const float4* asrc[4]; const float4* bsrc[4];
    int sts_off[4];
    #pragma unroll
    for (int t = 0; t < 4; t++) {
        int it = tid + 256 * t;
        int row = it >> 3, c4 = it & 7;
        int mm = m0 + row; if (mm > cnt - 1) mm = cnt - 1;
        asrc[t] = (const float4*)(A + (size_t)mm * KD) + c4;
        bsrc[t] = (const float4*)(W + (size_t)(n0 + row) * KD) + c4;
        sts_off[t] = row * LDP + c4 * 4;
    }

    float acc[4][4][4];
    #pragma unroll
    for (int mi = 0; mi < 4; mi++)
        #pragma unroll
        for (int nj = 0; nj < 4; nj++)
            #pragma unroll
            for (int r = 0; r < 4; r++) acc[mi][nj][r] = 0.f;

    const int NS = KD / 32;
    float4 ra[4], rb[4];
    #pragma unroll
    for (int t = 0; t < 4; t++) { ra[t] = asrc[t][0]; rb[t] = bsrc[t][0]; }
    #pragma unroll
    for (int t = 0; t < 4; t++) {
        *(float4*)(As + sts_off[t]) = rna4(ra[t]);
        *(float4*)(Bs + sts_off[t]) = rna4(rb[t]);
    }
    __syncthreads();

    for (int s = 0; s < NS; s++) {
        const int buf = s & 1;
        if (s + 1 < NS) {
            #pragma unroll
            for (int t = 0; t < 4; t++) { ra[t] = asrc[t][(s + 1) * 8]; rb[t] = bsrc[t][(s + 1) * 8]; }
        }
        const float* Ab = As + buf * 128 * LDP;
        const float* Bb = Bs + buf * 128 * LDP;
        const int q = lane >> 2, c = lane & 3;
        #pragma unroll
        for (int ks = 0; ks < 4; ks++) {
            const int kc = ks * 8 + c;
            uint32_t af[4][4];
            #pragma unroll
            for (int mi = 0; mi < 4; mi++) {
                const int r = wm * 64 + mi * 16 + q;
                af[mi][0] = __float_as_uint(Ab[r * LDP + kc]);
                af[mi][1] = __float_as_uint(Ab[(r + 8) * LDP + kc]);
                af[mi][2] = __float_as_uint(Ab[r * LDP + kc + 4]);
                af[mi][3] = __float_as_uint(Ab[(r + 8) * LDP + kc + 4]);
            }
            #pragma unroll
            for (int nj = 0; nj < 4; nj++) {
                const int n = wn * 32 + nj * 8 + q;
                uint32_t b0 = __float_as_uint(Bb[n * LDP + kc]);
                uint32_t b1 = __float_as_uint(Bb[n * LDP + kc + 4]);
                #pragma unroll
                for (int mi = 0; mi < 4; mi++)
                    mma_tf32(acc[mi][nj], af[mi][0], af[mi][1], af[mi][2], af[mi][3], b0, b1);
            }
        }
        if (s + 1 < NS) {
            __syncthreads();
            float* Aw = As + (buf ^ 1) * 128 * LDP;
            float* Bw = Bs + (buf ^ 1) * 128 * LDP;
            #pragma unroll
            for (int t = 0; t < 4; t++) {
                *(float4*)(Aw + sts_off[t]) = rna4(ra[t]);
                *(float4*)(Bw + sts_off[t]) = rna4(rb[t]);
            }
            __syncthreads();
        }
    }

    // ---- epilogue ----
    const int q = lane >> 2, c2 = (lane & 3) * 2;
    #pragma unroll
    for (int mi = 0; mi < 4; mi++) {
        const int mrel0 = wm * 64 + mi * 16 + q;
        #pragma unroll
        for (int half = 0; half < 2; half++) {
            const int mrel = mrel0 + half * 8;
            const int m = m0 + mrel;
            if (m >= cnt) continue;
            if (SCATTER) {
                const int   tok = g_tok[e * T_ + m];
                const float wt  = g_wt [e * T_ + m];
                float* op = out + (size_t)tok * D_;
                #pragma unroll
                for (int nj = 0; nj < 4; nj++) {
                    const int col = n0 + wn * 32 + nj * 8 + c2;
                    atomicAdd(op + col,     wt * acc[mi][nj][half * 2 + 0]);
                    atomicAdd(op + col + 1, wt * acc[mi][nj][half * 2 + 1]);
                }
            } else {
                float* op = out + (size_t)m * D_;
                #pragma unroll
                for (int nj = 0; nj < 4; nj++) {
                    const int col = n0 + wn * 32 + nj * 8 + c2;
                    *(float2*)(op + col) = make_float2(acc[mi][nj][half * 2 + 0],
                                                       acc[mi][nj][half * 2 + 1]);
                }
            }
        }
    }
}

// ---------------- launch ----------------
#define SMEM_BYTES (4 * 128 * LDP * 4)   // A+B double-buffered: 73728 B

extern "C" void kernel_launch(void* const* d_in, const int* in_sizes, int n_in,
                              void* d_out, int out_size) {
    const float* x  = (const float*)d_in[0];
    const float* gw = (const float*)d_in[2];
    const float* gb = (const float*)d_in[3];
    const float* gp = (const float*)d_in[4];
    const float* up = (const float*)d_in[5];
    const float* dp = (const float*)d_in[6];
    const float* sg = (const float*)d_in[7];
    const float* su = (const float*)d_in[8];
    const float* sd = (const float*)d_in[9];
    float* out = (float*)d_out;

    cudaFuncSetAttribute(mma_gu_kernel<true>,              cudaFuncAttributeMaxDynamicSharedMemorySize, SMEM_BYTES);
    cudaFuncSetAttribute(mma_gu_kernel<false>,             cudaFuncAttributeMaxDynamicSharedMemorySize, SMEM_BYTES);
    cudaFuncSetAttribute(mma_down_kernel<true,  INTER_>,   cudaFuncAttributeMaxDynamicSharedMemorySize, SMEM_BYTES);
    cudaFuncSetAttribute(mma_down_kernel<false, SH_INTER>, cudaFuncAttributeMaxDynamicSharedMemorySize, SMEM_BYTES);

    zero_counts_kernel<<<1, 32>>>();
    route_kernel<<<T_, 128>>>(x, gw, gb);

    // gate/up GEMMs
    mma_gu_kernel<true ><<<dim3(INTER_ / 64, T_ / 128, E_), 256, SMEM_BYTES>>>(x, gp, up);
    mma_gu_kernel<false><<<dim3(SH_INTER / 64, T_ / 128),   256, SMEM_BYTES>>>(x, sg, su);

    // down GEMMs: shared writes out (initializes), routed atomically accumulates
    mma_down_kernel<false, SH_INTER><<<dim3(D_ / 128, T_ / 128),      256, SMEM_BYTES>>>(sd, out);
    mma_down_kernel<true,  INTER_ ><<<dim3(D_ / 128, T_ / 128, E_),  256, SMEM_BYTES>>>(dp, out);
}

// round 4
// speedup vs baseline: 4.0120x; 1.5552x over previous
#include <cuda_runtime.h>
#include <math.h>
#include <stdint.h>

// Problem constants
#define T_       1024
#define D_       1024
#define E_       16
#define K_SEL    4
#define NGRP     4
#define INTER_   512
#define SH_INTER 1024
#define RSCALE   2.5f

#define LDP 36                        // padded smem row stride (floats)
#define BUFB (128 * LDP * 4)          // one buffer, bytes
#define NZ   18                       // 16 routed experts + 2 shared halves

// ---------------- device scratch ----------------
__device__ int   g_cnt[E_];
__device__ int   g_tok[E_ * T_];
__device__ float g_wt [E_ * T_];
__device__ float g_inter[(size_t)E_ * T_ * INTER_];
__device__ float g_hsh[(size_t)T_ * SH_INTER];

// ---------------- helpers ----------------
__device__ __forceinline__ uint32_t smem_u32(const void* p) {
    uint32_t a;
    asm("{ .reg .u64 t; cvta.to.shared.u64 t, %1; cvt.u32.u64 %0, t; }" : "=r"(a) : "l"(p));
    return a;
}
__device__ __forceinline__ void cp16(uint32_t s, const float* g) {
    asm volatile("cp.async.cg.shared.global [%0], [%1], 16;" :: "r"(s), "l"(g) : "memory");
}
#define CP_COMMIT() asm volatile("cp.async.commit_group;" ::: "memory")
#define CP_WAIT(n)  asm volatile("cp.async.wait_group %0;" :: "n"(n) : "memory")

__device__ __forceinline__ uint32_t lds_tf32(const float* p) {
    uint32_t u;
    asm("cvt.rna.tf32.f32 %0, %1;" : "=r"(u) : "f"(*p));
    return u;
}
__device__ __forceinline__ void mma_tf32(float c[4],
                                         uint32_t a0, uint32_t a1, uint32_t a2, uint32_t a3,
                                         uint32_t b0, uint32_t b1) {
    asm volatile(
        "mma.sync.aligned.m16n8k8.row.col.f32.tf32.tf32.f32 "
        "{%0,%1,%2,%3}, {%4,%5,%6,%7}, {%8,%9}, {%0,%1,%2,%3};"
        : "+f"(c[0]), "+f"(c[1]), "+f"(c[2]), "+f"(c[3])
        : "r"(a0), "r"(a1), "r"(a2), "r"(a3), "r"(b0), "r"(b1));
}
__device__ __forceinline__ float silu_mul(float g, float u) {
    return g / (1.f + expf(-g)) * u;
}

// ---------------- routing ----------------
__global__ void zero_counts_kernel() {
    if (threadIdx.x < E_) g_cnt[threadIdx.x] = 0;
}

__global__ void route_kernel(const float* __restrict__ x,
                             const float* __restrict__ gw,
                             const float* __restrict__ gb) {
    const int t = blockIdx.x;
    __shared__ float xs[D_];
    __shared__ float sc[E_];
    const int tid = threadIdx.x;  // 128
    const float4* xr = (const float4*)(x + (size_t)t * D_);
    float4* xs4 = (float4*)xs;
    for (int i = tid; i < D_ / 4; i += 128) xs4[i] = xr[i];
    __syncthreads();

    const int warp = tid >> 5, lane = tid & 31;
    for (int e = warp * 4; e < warp * 4 + 4; e++) {
        const float* w = gw + (size_t)e * D_;
        float p = 0.f;
        for (int j = lane; j < D_; j += 32) p += xs[j] * w[j];
        #pragma unroll
        for (int o = 16; o; o >>= 1) p += __shfl_xor_sync(0xffffffffu, p, o);
        if (lane == 0) sc[e] = 1.f / (1.f + expf(-p));
    }
    __syncthreads();

    if (tid == 0) {
        float s[E_];
        #pragma unroll
        for (int e = 0; e < E_; e++) s[e] = sc[e] + gb[e];
        float gsc[NGRP];
        #pragma unroll
        for (int g = 0; g < NGRP; g++) {
            float m1 = -1e30f, m2 = -1e30f;
            #pragma unroll
            for (int j = 0; j < 4; j++) {
                float v = s[g * 4 + j];
                if (v > m1) { m2 = m1; m1 = v; } else if (v > m2) { m2 = v; }
            }
            gsc[g] = m1 + m2;
        }
        int g1 = 0;
        for (int g = 1; g < NGRP; g++) if (gsc[g] > gsc[g1]) g1 = g;
        int g2 = -1;
        for (int g = 0; g < NGRP; g++) {
            if (g == g1) continue;
            if (g2 < 0 || gsc[g] > gsc[g2]) g2 = g;
        }
        float masked[E_];
        #pragma unroll
        for (int e = 0; e < E_; e++) {
            int g = e >> 2;
            masked[e] = (g == g1 || g == g2) ? s[e] : 0.f;
        }
        int idx[K_SEL];
        float w[K_SEL];
        bool used[E_];
        #pragma unroll
        for (int e = 0; e < E_; e++) used[e] = false;
        float wsum = 0.f;
        for (int k = 0; k < K_SEL; k++) {
            int best = -1; float bv = -1e30f;
            for (int e = 0; e < E_; e++) {
                if (used[e]) continue;
                if (masked[e] > bv) { bv = masked[e]; best = e; }
            }
            used[best] = true;
            idx[k] = best;
            w[k] = sc[best];
            wsum += w[k];
        }
        const float scale = RSCALE / wsum;
        for (int k = 0; k < K_SEL; k++) {
            int e = idx[k];
            int pos = atomicAdd(&g_cnt[e], 1);
            g_tok[e * T_ + pos] = t;
            g_wt [e * T_ + pos] = w[k] * scale;
        }
    }
}

// ================================================================
// GEMM 1 (unified): for z<16 routed expert z, z>=16 shared half (z-16).
// C = silu(X Wg^T) * (X Wu^T).  Block: 128 M x 64 N (gate), dual-B.
// ================================================================
__global__ void __launch_bounds__(256, 2) mma_gu_kernel(const float* __restrict__ X,
                                                        const float* __restrict__ gp,
                                                        const float* __restrict__ up,
                                                        const float* __restrict__ sg,
                                                        const float* __restrict__ su) {
    const int z = blockIdx.z;
    const bool routed = z < E_;
    const int cnt = routed ? g_cnt[z] : T_;
    const int m0  = blockIdx.y * 128;
    if (m0 >= cnt) return;
    const int n0 = blockIdx.x * 64;

    const float* Wg;
    const float* Wu;
    float* C;
    int ldc, cb;
    if (routed) {
        Wg = gp + ((size_t)z * INTER_ + n0) * D_;
        Wu = up + ((size_t)z * INTER_ + n0) * D_;
        C = g_inter + (size_t)z * T_ * INTER_;
        ldc = INTER_; cb = n0;
    } else {
        const int h = z - E_;
        Wg = sg + ((size_t)h * 512 + n0) * D_;
        Wu = su + ((size_t)h * 512 + n0) * D_;
        C = g_hsh;
        ldc = SH_INTER; cb = h * 512 + n0;
    }

    extern __shared__ float smem[];
    float* As = smem;                   // [2][128][LDP]
    float* Bs = smem + 2 * 128 * LDP;   // [2][128][LDP]
    const uint32_t sA = smem_u32(As);
    const uint32_t sB = smem_u32(Bs);

    const int tid = threadIdx.x, wid = tid >> 5, lane = tid & 31;
    const int wm = wid >> 2, wn = wid & 3;

    // per-thread cp.async plan: 4 A chunks + 4 B chunks (16B each) per stage
    const float* agl[4]; const float* bgl[4];
    uint32_t sa[4], sbo[4];
    #pragma unroll
    for (int t = 0; t < 4; t++) {
        int it = tid + 256 * t;
        int row = it >> 3, c4 = it & 7;
        int mm = m0 + row; if (mm > cnt - 1) mm = cnt - 1;
        int ar = routed ? g_tok[z * T_ + mm] : mm;
        agl[t] = X + (size_t)ar * D_ + c4 * 4;
        bgl[t] = ((row < 64) ? (Wg + (size_t)row * D_) : (Wu + (size_t)(row - 64) * D_)) + c4 * 4;
        uint32_t boff = (uint32_t)(row * LDP + c4 * 4) * 4u;
        sa[t]  = sA + boff;
        sbo[t] = sB + boff;
    }

    float acg[4][2][4], acu[4][2][4];
    #pragma unroll
    for (int mi = 0; mi < 4; mi++)
        #pragma unroll
        for (int nj = 0; nj < 2; nj++)
            #pragma unroll
            for (int r = 0; r < 4; r++) { acg[mi][nj][r] = 0.f; acu[mi][nj][r] = 0.f; }

    const int NS = D_ / 32;   // 32 stages
    const int q = lane >> 2, c = lane & 3;

    // prologue
    #pragma unroll
    for (int t = 0; t < 4; t++) { cp16(sa[t], agl[t]); cp16(sbo[t], bgl[t]); }
    CP_COMMIT();

    for (int s = 0; s < NS; s++) {
        if (s + 1 < NS) {
            const uint32_t bo = (uint32_t)(((s + 1) & 1) * BUFB);
            #pragma unroll
            for (int t = 0; t < 4; t++) {
                cp16(sa[t] + bo, agl[t] + (s + 1) * 32);
                cp16(sbo[t] + bo, bgl[t] + (s + 1) * 32);
            }
            CP_COMMIT();
            CP_WAIT(1);
        } else {
            CP_WAIT(0);
        }
        __syncthreads();

        const float* Ab = As + (s & 1) * 128 * LDP;
        const float* Bb = Bs + (s & 1) * 128 * LDP;
        #pragma unroll
        for (int ks = 0; ks < 4; ks++) {
            const int kc = ks * 8 + c;
            uint32_t af[4][4];
            #pragma unroll
            for (int mi = 0; mi < 4; mi++) {
                const int r = wm * 64 + mi * 16 + q;
                af[mi][0] = lds_tf32(&Ab[r * LDP + kc]);
                af[mi][1] = lds_tf32(&Ab[(r + 8) * LDP + kc]);
                af[mi][2] = lds_tf32(&Ab[r * LDP + kc + 4]);
                af[mi][3] = lds_tf32(&Ab[(r + 8) * LDP + kc + 4]);
            }
            #pragma unroll
            for (int nj = 0; nj < 2; nj++) {
                const int n = wn * 16 + nj * 8 + q;
                uint32_t bg0 = lds_tf32(&Bb[n * LDP + kc]);
                uint32_t bg1 = lds_tf32(&Bb[n * LDP + kc + 4]);
                uint32_t bu0 = lds_tf32(&Bb[(n + 64) * LDP + kc]);
                uint32_t bu1 = lds_tf32(&Bb[(n + 64) * LDP + kc + 4]);
                #pragma unroll
                for (int mi = 0; mi < 4; mi++) {
                    mma_tf32(acg[mi][nj], af[mi][0], af[mi][1], af[mi][2], af[mi][3], bg0, bg1);
                    mma_tf32(acu[mi][nj], af[mi][0], af[mi][1], af[mi][2], af[mi][3], bu0, bu1);
                }
            }
        }
        __syncthreads();
    }

    // epilogue: SwiGLU
    const int c2 = (lane & 3) * 2;
    #pragma unroll
    for (int mi = 0; mi < 4; mi++) {
        const int r0 = m0 + wm * 64 + mi * 16 + q;
        #pragma unroll
        for (int nj = 0; nj < 2; nj++) {
            const int col = cb + wn * 16 + nj * 8 + c2;
            if (r0 < cnt) {
                float2 v = make_float2(silu_mul(acg[mi][nj][0], acu[mi][nj][0]),
                                       silu_mul(acg[mi][nj][1], acu[mi][nj][1]));
                *(float2*)(C + (size_t)r0 * ldc + col) = v;
            }
            if (r0 + 8 < cnt) {
                float2 v = make_float2(silu_mul(acg[mi][nj][2], acu[mi][nj][2]),
                                       silu_mul(acg[mi][nj][3], acu[mi][nj][3]));
                *(float2*)(C + (size_t)(r0 + 8) * ldc + col) = v;
            }
        }
    }
}

// ================================================================
// GEMM 2 (unified): out += w * (A Wd^T), all via atomicAdd.
// z<16: A = g_inter[z] (K=512), scatter+weight.  z>=16: shared half, identity.
// Block 128 M x 128 N.
// ================================================================
__global__ void __launch_bounds__(256, 2) mma_down_kernel(const float* __restrict__ dp,
                                                          const float* __restrict__ sd,
                                                          float* __restrict__ out) {
    const int z = blockIdx.z;
    const bool routed = z < E_;
    const int cnt = routed ? g_cnt[z] : T_;
    const int m0  = blockIdx.y * 128;
    if (m0 >= cnt) return;
    const int n0 = blockIdx.x * 128;

    const float* A;
    const float* W;
    int lda, ldw;
    if (routed) {
        A = g_inter + (size_t)z * T_ * INTER_; lda = INTER_;
        W = dp + (size_t)z * D_ * INTER_;      ldw = INTER_;
    } else {
        const int h = z - E_;
        A = g_hsh + (size_t)h * 512; lda = SH_INTER;
        W = sd    + (size_t)h * 512; ldw = SH_INTER;
    }

    extern __shared__ float smem[];
    float* As = smem;
    float* Bs = smem + 2 * 128 * LDP;
    const uint32_t sA = smem_u32(As);
    const uint32_t sB = smem_u32(Bs);

    const int tid = threadIdx.x, wid = tid >> 5, lane = tid & 31;
    const int wm = wid >> 2, wn = wid & 3;

    const float* agl[4]; const float* bgl[4];
    uint32_t sa[4], sbo[4];
    #pragma unroll
    for (int t = 0; t < 4; t++) {
        int it = tid + 256 * t;
        int row = it >> 3, c4 = it & 7;
        int mm = m0 + row; if (mm > cnt - 1) mm = cnt - 1;
        agl[t] = A + (size_t)mm * lda + c4 * 4;
        bgl[t] = W + (size_t)(n0 + row) * ldw + c4 * 4;
        uint32_t boff = (uint32_t)(row * LDP + c4 * 4) * 4u;
        sa[t]  = sA + boff;
        sbo[t] = sB + boff;
    }

    float acc[4][4][4];
    #pragma unroll
    for (int mi = 0; mi < 4; mi++)
        #pragma unroll
        for (int nj = 0; nj < 4; nj++)
            #pragma unroll
            for (int r = 0; r < 4; r++) acc[mi][nj][r] = 0.f;

    const int NS = INTER_ / 32;   // 16 stages (K = 512 everywhere)
    const int q = lane >> 2, c = lane & 3;

    #pragma unroll
    for (int t = 0; t < 4; t++) { cp16(sa[t], agl[t]); cp16(sbo[t], bgl[t]); }
    CP_COMMIT();

    for (int s = 0; s < NS; s++) {
        if (s + 1 < NS) {
            const uint32_t bo = (uint32_t)(((s + 1) & 1) * BUFB);
            #pragma unroll
            for (int t = 0; t < 4; t++) {
                cp16(sa[t] + bo, agl[t] + (s + 1) * 32);
                cp16(sbo[t] + bo, bgl[t] + (s + 1) * 32);
            }
            CP_COMMIT();
            CP_WAIT(1);
        } else {
            CP_WAIT(0);
        }
        __syncthreads();

        const float* Ab = As + (s & 1) * 128 * LDP;
        const float* Bb = Bs + (s & 1) * 128 * LDP;
        #pragma unroll
        for (int ks = 0; ks < 4; ks++) {
            const int kc = ks * 8 + c;
            uint32_t af[4][4];
            #pragma unroll
            for (int mi = 0; mi < 4; mi++) {
                const int r = wm * 64 + mi * 16 + q;
                af[mi][0] = lds_tf32(&Ab[r * LDP + kc]);
                af[mi][1] = lds_tf32(&Ab[(r + 8) * LDP + kc]);
                af[mi][2] = lds_tf32(&Ab[r * LDP + kc + 4]);
                af[mi][3] = lds_tf32(&Ab[(r + 8) * LDP + kc + 4]);
            }
            #pragma unroll
            for (int nj = 0; nj < 4; nj++) {
                const int n = wn * 32 + nj * 8 + q;
                uint32_t b0 = lds_tf32(&Bb[n * LDP + kc]);
                uint32_t b1 = lds_tf32(&Bb[n * LDP + kc + 4]);
                #pragma unroll
                for (int mi = 0; mi < 4; mi++)
                    mma_tf32(acc[mi][nj], af[mi][0], af[mi][1], af[mi][2], af[mi][3], b0, b1);
            }
        }
        __syncthreads();
    }

    // epilogue: all contributions atomically accumulate
    const int c2 = (lane & 3) * 2;
    #pragma unroll
    for (int mi = 0; mi < 4; mi++) {
        #pragma unroll
        for (int half = 0; half < 2; half++) {
            const int m = m0 + wm * 64 + mi * 16 + q + half * 8;
            if (m >= cnt) continue;
            const int   tok = routed ? g_tok[z * T_ + m] : m;
            const float wt  = routed ? g_wt [z * T_ + m] : 1.f;
            float* op = out + (size_t)tok * D_;
            #pragma unroll
            for (int nj = 0; nj < 4; nj++) {
                const int col = n0 + wn * 32 + nj * 8 + c2;
                atomicAdd(op + col,     wt * acc[mi][nj][half * 2 + 0]);
                atomicAdd(op + col + 1, wt * acc[mi][nj][half * 2 + 1]);
            }
        }
    }
}

// ---------------- launch ----------------
#define SMEM_BYTES (4 * 128 * LDP * 4)   // 73728 B

extern "C" void kernel_launch(void* const* d_in, const int* in_sizes, int n_in,
                              void* d_out, int out_size) {
    const float* x  = (const float*)d_in[0];
    const float* gw = (const float*)d_in[2];
    const float* gb = (const float*)d_in[3];
    const float* gp = (const float*)d_in[4];
    const float* up = (const float*)d_in[5];
    const float* dp = (const float*)d_in[6];
    const float* sg = (const float*)d_in[7];
    const float* su = (const float*)d_in[8];
    const float* sd = (const float*)d_in[9];
    float* out = (float*)d_out;

    cudaFuncSetAttribute(mma_gu_kernel,   cudaFuncAttributeMaxDynamicSharedMemorySize, SMEM_BYTES);
    cudaFuncSetAttribute(mma_down_kernel, cudaFuncAttributeMaxDynamicSharedMemorySize, SMEM_BYTES);

    cudaMemsetAsync(out, 0, (size_t)T_ * D_ * sizeof(float), 0);
    zero_counts_kernel<<<1, 32>>>();
    route_kernel<<<T_, 128>>>(x, gw, gb);

    mma_gu_kernel<<<dim3(8, T_ / 128, NZ), 256, SMEM_BYTES>>>(x, gp, up, sg, su);
    mma_down_kernel<<<dim3(D_ / 128, T_ / 128, NZ), 256, SMEM_BYTES>>>(dp, sd, out);
}